// round 4
// baseline (speedup 1.0000x reference)
#include <cuda_runtime.h>
#include <cuda_bf16.h>
#include <stdint.h>

#define NN 100000
#define EE 640000
#define DD 128
#define NB_SCAN ((NN + 255) / 256)   // 391
#define TILE_M 64
#define GEMM_SMEM ((DD * TILE_M + DD * 256) * 4)   // 163840 bytes

// ---------------- scratch (device globals; no allocation allowed) -------------
__device__ float g_h1[NN * DD];      // nodes @ W1 + b1
__device__ float g_conv[NN * DD];    // (nodes @ W2 + b2) * rsqrt(send_deg)
__device__ int   g_send_deg[NN];
__device__ int   g_recv_deg[NN];
__device__ int   g_cursor[NN];
__device__ int   g_row_ptr[NN + 1];
__device__ int   g_bsum[NB_SCAN];
__device__ int   g_edge_src[EE];     // senders reordered into CSR-by-receiver
__device__ float g_an[DD];           // column sums of h
__device__ float g_gvec[DD];         // globals @ W3 + b3

// ---------------- f32x2 helpers ----------------------------------------------
__device__ __forceinline__ unsigned long long pack2(float x) {
    unsigned long long r;
    asm("mov.b64 %0, {%1, %1};" : "=l"(r) : "f"(x));
    return r;
}
__device__ __forceinline__ unsigned long long fma2(unsigned long long a,
                                                   unsigned long long b,
                                                   unsigned long long c) {
    unsigned long long d;
    asm("fma.rn.f32x2 %0, %1, %2, %3;" : "=l"(d) : "l"(a), "l"(b), "l"(c));
    return d;
}
__device__ __forceinline__ float2 unpack2(unsigned long long u) {
    float2 f;
    asm("mov.b64 {%0, %1}, %2;" : "=f"(f.x), "=f"(f.y) : "l"(u));
    return f;
}

// ---------------- init --------------------------------------------------------
__global__ void k_init() {
    int i = blockIdx.x * blockDim.x + threadIdx.x;
    if (i < NN) { g_send_deg[i] = 0; g_recv_deg[i] = 0; g_cursor[i] = 0; }
    if (i < DD) g_an[i] = 0.f;
    if (i == 0) g_row_ptr[NN] = EE;
}

// ---------------- degree histogram -------------------------------------------
__global__ void k_deg(const int* __restrict__ senders,
                      const int* __restrict__ receivers) {
    int e = blockIdx.x * blockDim.x + threadIdx.x;
    if (e < EE) {
        atomicAdd(&g_send_deg[senders[e]], 1);
        atomicAdd(&g_recv_deg[receivers[e]], 1);
    }
}

// ---------------- 3-phase exclusive scan of recv_deg -> row_ptr --------------
__global__ void k_scan1() {
    __shared__ int s[256];
    int i = blockIdx.x * 256 + threadIdx.x;
    int v = (i < NN) ? g_recv_deg[i] : 0;
    s[threadIdx.x] = v;
    __syncthreads();
#pragma unroll
    for (int off = 1; off < 256; off <<= 1) {
        int t = (threadIdx.x >= off) ? s[threadIdx.x - off] : 0;
        __syncthreads();
        s[threadIdx.x] += t;
        __syncthreads();
    }
    if (i < NN) g_row_ptr[i] = s[threadIdx.x] - v;   // exclusive
    if (threadIdx.x == 255) g_bsum[blockIdx.x] = s[255];
}

__global__ void k_scan2() {   // 1 block, 512 threads over NB_SCAN block sums
    __shared__ int s[512];
    int v = (threadIdx.x < NB_SCAN) ? g_bsum[threadIdx.x] : 0;
    s[threadIdx.x] = v;
    __syncthreads();
#pragma unroll
    for (int off = 1; off < 512; off <<= 1) {
        int t = (threadIdx.x >= off) ? s[threadIdx.x - off] : 0;
        __syncthreads();
        s[threadIdx.x] += t;
        __syncthreads();
    }
    if (threadIdx.x < NB_SCAN) g_bsum[threadIdx.x] = s[threadIdx.x] - v; // exclusive
}

__global__ void k_scan3() {
    int i = blockIdx.x * 256 + threadIdx.x;
    if (i < NN) g_row_ptr[i] += g_bsum[i >> 8];
}

// ---------------- CSR fill ----------------------------------------------------
__global__ void k_fill(const int* __restrict__ senders,
                       const int* __restrict__ receivers) {
    int e = blockIdx.x * blockDim.x + threadIdx.x;
    if (e < EE) {
        int r = receivers[e];
        int pos = g_row_ptr[r] + atomicAdd(&g_cursor[r], 1);
        g_edge_src[pos] = senders[e];
    }
}

// ---------------- fused dual GEMM: h1 = X@W1+b1 ; conv = (X@W2+b2)*rs --------
// block: 256 threads, C-tile 64 rows x 256 cols (cols 0..127 -> W1, 128..255 -> W2)
// thread microtile: 8 rows x 8 cols, cols as 4 f32x2 pairs at (2*tc + 64*j).
__global__ void __launch_bounds__(256, 1)
k_gemm(const float* __restrict__ nodes,
       const float* __restrict__ W1, const float* __restrict__ b1,
       const float* __restrict__ W2, const float* __restrict__ b2) {
    extern __shared__ float sm[];
    float* ns = sm;                 // [128][64]  nodes tile, transposed
    float* wt = sm + DD * TILE_M;   // [128][256] concatenated weights
    int tid = threadIdx.x;
    int m0 = blockIdx.x * TILE_M;

    // load weights (W1 | W2) -> wt[k][0..255]
    float4* wt4 = (float4*)wt;
    for (int idx = tid; idx < 128 * 64; idx += 256) {
        int k = idx >> 6;
        int c = (idx & 63) << 2;
        float4 v;
        if (c < 128) v = *(const float4*)(W1 + k * 128 + c);
        else         v = *(const float4*)(W2 + k * 128 + (c - 128));
        wt4[idx] = v;
    }
    // load nodes tile transposed -> ns[k][m]
    for (int idx = tid; idx < TILE_M * 32; idx += 256) {
        int row = idx >> 5;
        int kc = (idx & 31) << 2;
        float4 v = make_float4(0.f, 0.f, 0.f, 0.f);
        int gr = m0 + row;
        if (gr < NN) v = *(const float4*)(nodes + gr * 128 + kc);
        ns[(kc + 0) * TILE_M + row] = v.x;
        ns[(kc + 1) * TILE_M + row] = v.y;
        ns[(kc + 2) * TILE_M + row] = v.z;
        ns[(kc + 3) * TILE_M + row] = v.w;
    }
    __syncthreads();

    int tc = tid & 31, tr = tid >> 5;
    unsigned long long acc[8][4];
#pragma unroll
    for (int i = 0; i < 8; i++)
#pragma unroll
        for (int j = 0; j < 4; j++) acc[i][j] = 0ull;

    const float* nsb = ns + tr * 8;
    const float* wtb = wt + tc * 2;

#pragma unroll 4
    for (int k = 0; k < 128; k++) {
        float4 a0 = *(const float4*)(nsb + k * TILE_M);       // broadcast
        float4 a1 = *(const float4*)(nsb + k * TILE_M + 4);
        unsigned long long bb0 = *(const unsigned long long*)(wtb + k * 256);
        unsigned long long bb1 = *(const unsigned long long*)(wtb + k * 256 + 64);
        unsigned long long bb2 = *(const unsigned long long*)(wtb + k * 256 + 128);
        unsigned long long bb3 = *(const unsigned long long*)(wtb + k * 256 + 192);
        float av[8] = {a0.x, a0.y, a0.z, a0.w, a1.x, a1.y, a1.z, a1.w};
#pragma unroll
        for (int i = 0; i < 8; i++) {
            unsigned long long a2 = pack2(av[i]);
            acc[i][0] = fma2(a2, bb0, acc[i][0]);
            acc[i][1] = fma2(a2, bb1, acc[i][1]);
            acc[i][2] = fma2(a2, bb2, acc[i][2]);
            acc[i][3] = fma2(a2, bb3, acc[i][3]);
        }
    }

    // epilogue
#pragma unroll
    for (int i = 0; i < 8; i++) {
        int gr = m0 + tr * 8 + i;
        if (gr >= NN) continue;
        float inv = rsqrtf(fmaxf((float)g_send_deg[gr], 1.f));
#pragma unroll
        for (int j = 0; j < 4; j++) {
            int c = tc * 2 + 64 * j;
            float2 v = unpack2(acc[i][j]);
            if (c < 128) {
                v.x += b1[c];
                v.y += b1[c + 1];
                *(float2*)(g_h1 + gr * 128 + c) = v;
            } else {
                int cc = c - 128;
                v.x = (v.x + b2[cc]) * inv;
                v.y = (v.y + b2[cc + 1]) * inv;
                *(float2*)(g_conv + gr * 128 + cc) = v;
            }
        }
    }
}

// ---------------- gvec = globals @ W3 + b3 ------------------------------------
__global__ void k_gvec(const float* __restrict__ g,
                       const float* __restrict__ W3,
                       const float* __restrict__ b3) {
    int c = threadIdx.x;   // 128 threads
    __shared__ float gs[128];
    gs[c] = g[c];
    __syncthreads();
    float acc = b3[c];
#pragma unroll 8
    for (int k = 0; k < 128; k++) acc += gs[k] * W3[k * 128 + c];
    g_gvec[c] = acc;
}

// ---------------- edge aggregation + epilogue ---------------------------------
#define AGG_BLOCKS 2048
__global__ void __launch_bounds__(256)
k_agg(const float* __restrict__ nodes, float* __restrict__ out) {
    __shared__ float colsum[128];
    int tid = threadIdx.x;
    if (tid < 128) colsum[tid] = 0.f;
    __syncthreads();
    int lane = tid & 31, warp = tid >> 5;
    const float4* conv4  = (const float4*)g_conv;
    const float4* h14    = (const float4*)g_h1;
    const float4* nodes4 = (const float4*)nodes;
    float4* out4 = (float4*)out;
    float4 gv = ((const float4*)g_gvec)[lane];
    float sx = 0.f, sy = 0.f, sz = 0.f, sw = 0.f;

    for (int r = blockIdx.x * 8 + warp; r < NN; r += AGG_BLOCKS * 8) {
        int b = g_row_ptr[r];
        int e = g_row_ptr[r + 1];
        float ax = 0.f, ay = 0.f, az = 0.f, aw = 0.f;
        for (int i = b; i < e; i++) {
            int s = g_edge_src[i];
            float4 v = conv4[s * 32 + lane];
            ax += v.x; ay += v.y; az += v.z; aw += v.w;
        }
        float rs = rsqrtf(fmaxf((float)(e - b), 1.f));   // recv_deg == e-b
        float4 h = h14[r * 32 + lane];
        float4 nv = nodes4[r * 32 + lane];
        float4 o;
        o.x = fmaxf(h.x + ax * rs + gv.x, 0.f) + nv.x;
        o.y = fmaxf(h.y + ay * rs + gv.y, 0.f) + nv.y;
        o.z = fmaxf(h.z + az * rs + gv.z, 0.f) + nv.z;
        o.w = fmaxf(h.w + aw * rs + gv.w, 0.f) + nv.w;
        out4[r * 32 + lane] = o;
        sx += o.x; sy += o.y; sz += o.z; sw += o.w;
    }
    atomicAdd(&colsum[lane * 4 + 0], sx);
    atomicAdd(&colsum[lane * 4 + 1], sy);
    atomicAdd(&colsum[lane * 4 + 2], sz);
    atomicAdd(&colsum[lane * 4 + 3], sw);
    __syncthreads();
    if (tid < 128) atomicAdd(&g_an[tid], colsum[tid]);
}

// ---------------- global update -----------------------------------------------
__global__ void k_gnew(const float* __restrict__ g,
                       const float* __restrict__ Wg,
                       const float* __restrict__ bg,
                       float* __restrict__ out) {
    int c = threadIdx.x;   // 128 threads
    __shared__ float av[128], gvs[128];
    av[c] = g_an[c];
    gvs[c] = g[c];
    __syncthreads();
    float acc = bg[c];
#pragma unroll 8
    for (int k = 0; k < 128; k++) acc += av[k] * Wg[k * 128 + c];
#pragma unroll 8
    for (int k = 0; k < 128; k++) acc += gvs[k] * Wg[(128 + k) * 128 + c];
    out[NN * DD + c] = gvs[c] + fmaxf(acc, 0.f);
}

// ---------------- launch ------------------------------------------------------
extern "C" void kernel_launch(void* const* d_in, const int* in_sizes, int n_in,
                              void* d_out, int out_size) {
    const float* nodes    = (const float*)d_in[0];
    const float* globals_ = (const float*)d_in[1];
    const int*   senders  = (const int*)d_in[2];
    const int*   receivers= (const int*)d_in[3];
    const float* W1w = (const float*)d_in[4];
    const float* W1b = (const float*)d_in[5];
    const float* W2w = (const float*)d_in[6];
    const float* W2b = (const float*)d_in[7];
    const float* W3w = (const float*)d_in[8];
    const float* W3b = (const float*)d_in[9];
    const float* Wgw = (const float*)d_in[10];
    const float* Wgb = (const float*)d_in[11];
    float* out = (float*)d_out;

    cudaFuncSetAttribute(k_gemm, cudaFuncAttributeMaxDynamicSharedMemorySize,
                         GEMM_SMEM);

    k_init <<<(NN + 255) / 256, 256>>>();
    k_deg  <<<(EE + 255) / 256, 256>>>(senders, receivers);
    k_scan1<<<NB_SCAN, 256>>>();
    k_scan2<<<1, 512>>>();
    k_scan3<<<(NN + 255) / 256, 256>>>();
    k_fill <<<(EE + 255) / 256, 256>>>(senders, receivers);
    k_gemm <<<(NN + TILE_M - 1) / TILE_M, 256, GEMM_SMEM>>>(nodes, W1w, W1b, W2w, W2b);
    k_gvec <<<1, 128>>>(globals_, W3w, W3b);
    k_agg  <<<AGG_BLOCKS, 256>>>(nodes, out);
    k_gnew <<<1, 128>>>(globals_, Wgw, Wgb, out);
}

// round 10
// speedup vs baseline: 1.3814x; 1.3814x over previous
#include <cuda_runtime.h>
#include <cuda_bf16.h>
#include <stdint.h>

#define NN 100000
#define EE 640000
#define DD 128
#define NB_SCAN ((NN + 255) / 256)   // 391

// ---------------- scratch (device globals; no allocation allowed) -------------
__device__ float g_h1[NN * DD];      // nodes @ W1 + b1
__device__ float g_conv[NN * DD];    // (nodes @ W2 + b2) * rsqrt(send_deg)
__device__ int   g_send_deg[NN];
__device__ int   g_recv_deg[NN];
__device__ int   g_cursor[NN];
__device__ int   g_row_ptr[NN + 1];
__device__ int   g_bsum[NB_SCAN];
__device__ int   g_edge_src[EE];     // senders reordered into CSR-by-receiver
__device__ float g_an[DD];           // column sums of h
__device__ float g_gvec[DD];         // globals @ W3 + b3

// ---------------- init --------------------------------------------------------
__global__ void k_init() {
    int i = blockIdx.x * blockDim.x + threadIdx.x;
    if (i < NN) { g_send_deg[i] = 0; g_recv_deg[i] = 0; g_cursor[i] = 0; }
    if (i < DD) g_an[i] = 0.f;
    if (i == 0) g_row_ptr[NN] = EE;
}

// ---------------- degree histogram -------------------------------------------
__global__ void k_deg(const int* __restrict__ senders,
                      const int* __restrict__ receivers) {
    int e = blockIdx.x * blockDim.x + threadIdx.x;
    if (e < EE) {
        atomicAdd(&g_send_deg[senders[e]], 1);
        atomicAdd(&g_recv_deg[receivers[e]], 1);
    }
}

// ---------------- 3-phase exclusive scan of recv_deg -> row_ptr --------------
__global__ void k_scan1() {
    __shared__ int s[256];
    int i = blockIdx.x * 256 + threadIdx.x;
    int v = (i < NN) ? g_recv_deg[i] : 0;
    s[threadIdx.x] = v;
    __syncthreads();
#pragma unroll
    for (int off = 1; off < 256; off <<= 1) {
        int t = (threadIdx.x >= off) ? s[threadIdx.x - off] : 0;
        __syncthreads();
        s[threadIdx.x] += t;
        __syncthreads();
    }
    if (i < NN) g_row_ptr[i] = s[threadIdx.x] - v;   // exclusive
    if (threadIdx.x == 255) g_bsum[blockIdx.x] = s[255];
}

__global__ void k_scan2() {   // 1 block, 512 threads over NB_SCAN block sums
    __shared__ int s[512];
    int v = (threadIdx.x < NB_SCAN) ? g_bsum[threadIdx.x] : 0;
    s[threadIdx.x] = v;
    __syncthreads();
#pragma unroll
    for (int off = 1; off < 512; off <<= 1) {
        int t = (threadIdx.x >= off) ? s[threadIdx.x - off] : 0;
        __syncthreads();
        s[threadIdx.x] += t;
        __syncthreads();
    }
    if (threadIdx.x < NB_SCAN) g_bsum[threadIdx.x] = s[threadIdx.x] - v; // exclusive
}

__global__ void k_scan3() {
    int i = blockIdx.x * 256 + threadIdx.x;
    if (i < NN) g_row_ptr[i] += g_bsum[i >> 8];
}

// ---------------- CSR fill ----------------------------------------------------
__global__ void k_fill(const int* __restrict__ senders,
                       const int* __restrict__ receivers) {
    int e = blockIdx.x * blockDim.x + threadIdx.x;
    if (e < EE) {
        int r = receivers[e];
        int pos = g_row_ptr[r] + atomicAdd(&g_cursor[r], 1);
        g_edge_src[pos] = senders[e];
    }
}

// =============================================================================
// mma.sync tf32 dual GEMM:  C[64 x 256] = A[64 x 128] @ (W1 | W2)
// arch-portable PTX (sm_80+) -> works at compute_103 target, runs on HMMA pipe.
// A in smem stride 132 floats (conflict-free frag loads), W k-major stride 264.
// 8 warps: wm = wid>>2 (2 x 32 rows), wn = wid&3 (4 x 64 cols).
// =============================================================================

#define GT_TM 64
#define GT_TN 256
#define A_STR 132
#define B_STR 264
// smem floats: A 64*132=8448 | W 128*264=33792 | bias 256 | inv 64
#define SMF_A    0
#define SMF_W    8448
#define SMF_BIAS (8448 + 33792)
#define SMF_INV  (SMF_BIAS + 256)
#define SM_TOTAL ((SMF_INV + 64) * 4)   // 170240 bytes

static __device__ __forceinline__ float to_tf32(float x) {
    float y;
    asm("cvt.rna.tf32.f32 %0, %1;" : "=f"(y) : "f"(x));
    return y;
}

__global__ void __launch_bounds__(256, 1)
k_gemm_mma(const float* __restrict__ nodes,
           const float* __restrict__ W1, const float* __restrict__ b1,
           const float* __restrict__ W2, const float* __restrict__ b2) {
    extern __shared__ float sm[];
    float* sa = sm + SMF_A;
    float* sw = sm + SMF_W;
    float* sb = sm + SMF_BIAS;
    float* sinv = sm + SMF_INV;
    int tid = threadIdx.x;
    int m0 = blockIdx.x * GT_TM;

    if (tid < 128) { sb[tid] = b1[tid]; sb[128 + tid] = b2[tid]; }
    if (tid >= 128 && tid < 192) {
        int r = tid - 128;
        int gr = m0 + r;
        float d = (gr < NN) ? (float)g_send_deg[gr] : 1.f;
        sinv[r] = rsqrtf(fmaxf(d, 1.f));
    }

    // A tile: 64 rows x 128 cols, tf32-rounded
    for (int idx = tid; idx < GT_TM * 32; idx += 256) {
        int m = idx >> 5;
        int k4 = (idx & 31) << 2;
        int gr = m0 + m;
        float4 v = make_float4(0.f, 0.f, 0.f, 0.f);
        if (gr < NN) v = *(const float4*)(nodes + gr * 128 + k4);
        v.x = to_tf32(v.x); v.y = to_tf32(v.y);
        v.z = to_tf32(v.z); v.w = to_tf32(v.w);
        *(float4*)(sa + m * A_STR + k4) = v;
    }
    // W tile: k-major [128][256] = (W1 | W2), tf32-rounded
    for (int idx = tid; idx < 8192; idx += 256) {
        int wsel = idx >> 12;
        int rem = idx & 4095;
        int k = rem >> 5;
        int n4 = (rem & 31) << 2;
        const float* src = wsel ? W2 : W1;
        float4 v = *(const float4*)(src + k * 128 + n4);
        v.x = to_tf32(v.x); v.y = to_tf32(v.y);
        v.z = to_tf32(v.z); v.w = to_tf32(v.w);
        *(float4*)(sw + k * B_STR + wsel * 128 + n4) = v;
    }
    __syncthreads();

    int wid = tid >> 5, l = tid & 31;
    int wn = wid & 3, wm = wid >> 2;
    int lr = l >> 2, lc = l & 3;

    const float* Ab = sa + (wm * 32 + lr) * A_STR + lc;
    const float* Bb = sw + lc * B_STR + wn * 64 + lr;

    float acc[2][8][4];
#pragma unroll
    for (int mt = 0; mt < 2; mt++)
#pragma unroll
        for (int nt = 0; nt < 8; nt++)
#pragma unroll
            for (int j = 0; j < 4; j++) acc[mt][nt][j] = 0.f;

#pragma unroll 4
    for (int kc = 0; kc < 16; kc++) {
        int k0 = kc * 8;
        uint32_t af[2][4];
#pragma unroll
        for (int mt = 0; mt < 2; mt++) {
            const float* ap = Ab + mt * 16 * A_STR + k0;
            af[mt][0] = __float_as_uint(ap[0]);
            af[mt][1] = __float_as_uint(ap[8 * A_STR]);
            af[mt][2] = __float_as_uint(ap[4]);
            af[mt][3] = __float_as_uint(ap[8 * A_STR + 4]);
        }
        uint32_t bf[8][2];
#pragma unroll
        for (int nt = 0; nt < 8; nt++) {
            const float* bp = Bb + k0 * B_STR + nt * 8;
            bf[nt][0] = __float_as_uint(bp[0]);
            bf[nt][1] = __float_as_uint(bp[4 * B_STR]);
        }
#pragma unroll
        for (int mt = 0; mt < 2; mt++)
#pragma unroll
            for (int nt = 0; nt < 8; nt++) {
                asm volatile(
                    "mma.sync.aligned.m16n8k8.row.col.f32.tf32.tf32.f32 "
                    "{%0,%1,%2,%3}, {%4,%5,%6,%7}, {%8,%9}, {%0,%1,%2,%3};"
                    : "+f"(acc[mt][nt][0]), "+f"(acc[mt][nt][1]),
                      "+f"(acc[mt][nt][2]), "+f"(acc[mt][nt][3])
                    : "r"(af[mt][0]), "r"(af[mt][1]),
                      "r"(af[mt][2]), "r"(af[mt][3]),
                      "r"(bf[nt][0]), "r"(bf[nt][1]));
            }
    }

    // epilogue: c0,c1 -> (row, 2lc..2lc+1), c2,c3 -> (row+8, same cols)
    int conv_half = (wn >= 2);
    float* base = conv_half ? g_conv : g_h1;
#pragma unroll
    for (int mt = 0; mt < 2; mt++) {
        int lrow = wm * 32 + mt * 16 + lr;       // local row 0..63
        int r0 = m0 + lrow;
        int r1 = r0 + 8;
        float i0 = conv_half ? sinv[lrow] : 1.f;
        float i1 = conv_half ? sinv[lrow + 8] : 1.f;
#pragma unroll
        for (int nt = 0; nt < 8; nt++) {
            int c = wn * 64 + nt * 8 + 2 * lc;   // 0..255
            float bx = sb[c], by = sb[c + 1];
            int cc = c & 127;
            if (r0 < NN) {
                float2 v;
                v.x = (acc[mt][nt][0] + bx) * i0;
                v.y = (acc[mt][nt][1] + by) * i0;
                *(float2*)(base + (size_t)r0 * 128 + cc) = v;
            }
            if (r1 < NN) {
                float2 v;
                v.x = (acc[mt][nt][2] + bx) * i1;
                v.y = (acc[mt][nt][3] + by) * i1;
                *(float2*)(base + (size_t)r1 * 128 + cc) = v;
            }
        }
    }
}

// ---------------- gvec = globals @ W3 + b3 ------------------------------------
__global__ void k_gvec(const float* __restrict__ g,
                       const float* __restrict__ W3,
                       const float* __restrict__ b3) {
    int c = threadIdx.x;   // 128 threads
    __shared__ float gs[128];
    gs[c] = g[c];
    __syncthreads();
    float acc = b3[c];
#pragma unroll 8
    for (int k = 0; k < 128; k++) acc += gs[k] * W3[k * 128 + c];
    g_gvec[c] = acc;
}

// ---------------- edge aggregation + epilogue ---------------------------------
#define AGG_BLOCKS 2048
__global__ void __launch_bounds__(256)
k_agg(const float* __restrict__ nodes, float* __restrict__ out) {
    __shared__ float colsum[128];
    int tid = threadIdx.x;
    if (tid < 128) colsum[tid] = 0.f;
    __syncthreads();
    int lane = tid & 31, warp = tid >> 5;
    const float4* conv4  = (const float4*)g_conv;
    const float4* h14    = (const float4*)g_h1;
    const float4* nodes4 = (const float4*)nodes;
    float4* out4 = (float4*)out;
    float4 gv = ((const float4*)g_gvec)[lane];
    float sx = 0.f, sy = 0.f, sz = 0.f, sw = 0.f;

    for (int r = blockIdx.x * 8 + warp; r < NN; r += AGG_BLOCKS * 8) {
        int b = g_row_ptr[r];
        int e = g_row_ptr[r + 1];
        float ax = 0.f, ay = 0.f, az = 0.f, aw = 0.f;
        for (int i = b; i < e; i++) {
            int s = g_edge_src[i];
            float4 v = conv4[s * 32 + lane];
            ax += v.x; ay += v.y; az += v.z; aw += v.w;
        }
        float rs = rsqrtf(fmaxf((float)(e - b), 1.f));   // recv_deg == e-b
        float4 h = h14[r * 32 + lane];
        float4 nv = nodes4[r * 32 + lane];
        float4 o;
        o.x = fmaxf(h.x + ax * rs + gv.x, 0.f) + nv.x;
        o.y = fmaxf(h.y + ay * rs + gv.y, 0.f) + nv.y;
        o.z = fmaxf(h.z + az * rs + gv.z, 0.f) + nv.z;
        o.w = fmaxf(h.w + aw * rs + gv.w, 0.f) + nv.w;
        out4[r * 32 + lane] = o;
        sx += o.x; sy += o.y; sz += o.z; sw += o.w;
    }
    atomicAdd(&colsum[lane * 4 + 0], sx);
    atomicAdd(&colsum[lane * 4 + 1], sy);
    atomicAdd(&colsum[lane * 4 + 2], sz);
    atomicAdd(&colsum[lane * 4 + 3], sw);
    __syncthreads();
    if (tid < 128) atomicAdd(&g_an[tid], colsum[tid]);
}

// ---------------- global update -----------------------------------------------
__global__ void k_gnew(const float* __restrict__ g,
                       const float* __restrict__ Wg,
                       const float* __restrict__ bg,
                       float* __restrict__ out) {
    int c = threadIdx.x;   // 128 threads
    __shared__ float av[128], gvs[128];
    av[c] = g_an[c];
    gvs[c] = g[c];
    __syncthreads();
    float acc = bg[c];
#pragma unroll 8
    for (int k = 0; k < 128; k++) acc += av[k] * Wg[k * 128 + c];
#pragma unroll 8
    for (int k = 0; k < 128; k++) acc += gvs[k] * Wg[(128 + k) * 128 + c];
    out[NN * DD + c] = gvs[c] + fmaxf(acc, 0.f);
}

// ---------------- launch ------------------------------------------------------
extern "C" void kernel_launch(void* const* d_in, const int* in_sizes, int n_in,
                              void* d_out, int out_size) {
    const float* nodes    = (const float*)d_in[0];
    const float* globals_ = (const float*)d_in[1];
    const int*   senders  = (const int*)d_in[2];
    const int*   receivers= (const int*)d_in[3];
    const float* W1w = (const float*)d_in[4];
    const float* W1b = (const float*)d_in[5];
    const float* W2w = (const float*)d_in[6];
    const float* W2b = (const float*)d_in[7];
    const float* W3w = (const float*)d_in[8];
    const float* W3b = (const float*)d_in[9];
    const float* Wgw = (const float*)d_in[10];
    const float* Wgb = (const float*)d_in[11];
    float* out = (float*)d_out;

    cudaFuncSetAttribute(k_gemm_mma, cudaFuncAttributeMaxDynamicSharedMemorySize,
                         SM_TOTAL);

    k_init <<<(NN + 255) / 256, 256>>>();
    k_deg  <<<(EE + 255) / 256, 256>>>(senders, receivers);
    k_scan1<<<NB_SCAN, 256>>>();
    k_scan2<<<1, 512>>>();
    k_scan3<<<(NN + 255) / 256, 256>>>();
    k_fill <<<(EE + 255) / 256, 256>>>(senders, receivers);
    k_gemm_mma<<<(NN + GT_TM - 1) / GT_TM, 256, SM_TOTAL>>>(nodes, W1w, W1b, W2w, W2b);
    k_gvec <<<1, 128>>>(globals_, W3w, W3b);
    k_agg  <<<AGG_BLOCKS, 256>>>(nodes, out);
    k_gnew <<<1, 128>>>(globals_, Wgw, Wgb, out);
}